// round 15
// baseline (speedup 1.0000x reference)
#include <cuda_runtime.h>
#include <cuda_fp16.h>
#include <mma.h>
#include <cstdint>

using namespace nvcuda;

#define N_TOK 4096
#define DIM   1024
#define NEXP  8
#define HDIM  2048
#define NSLOT 8192
#define PAD   128
#define GATE_BLOCKS (N_TOK / 8)   // 512

// gemm tiling: block 128x128, 4 warps (2x2), warp tile 64x64, BK=32, 3 stages
#define TM 128
#define TN 128
#define BK 32
#define NTH 128
#define LDB 40            // smem row stride in halves (80B)
#define LDC 68            // epilogue fp32 row stride

#define STAGE_H (TM * LDB + TN * LDB)     // halves per stage (10240)
#define SMEM_BYTES (3 * STAGE_H * 2)      // 61440 B; epilogue overlay 34816 B fits

// ---------------- scratch (device globals) ----------------------------------
__device__ __align__(256) __half g_xh[(size_t)N_TOK * DIM];           // x in fp16
__device__ __align__(256) __half g_H [(size_t)(NSLOT + PAD) * HDIM];  // relu out fp16
__device__ __align__(256) __half g_w1h[(size_t)NEXP * HDIM * DIM];
__device__ __align__(256) __half g_w2h[(size_t)NEXP * DIM * HDIM];
__device__ int   g_expert_tok[NSLOT];
__device__ float g_expert_w[NSLOT];
__device__ int   g_tok_e[N_TOK * 2];
__device__ float g_tok_w[N_TOK * 2];
__device__ int   g_counts[NEXP];
__device__ int   g_cursor[NEXP];
__device__ int   g_offsets[NEXP + 1];
__device__ int   g_top1_arr[NEXP];
__device__ int   g_nt;
// per-gate-block partials (plain stores in gate; reduced in route_kernel)
__device__ float g_part_colsum[GATE_BLOCKS * NEXP];
__device__ int   g_part_counts[GATE_BLOCKS * NEXP];
__device__ int   g_part_top1[GATE_BLOCKS * NEXP];
__device__ int   g_part_nt[GATE_BLOCKS];

// ---------------- helpers ---------------------------------------------------
__device__ __forceinline__ uint32_t smem_u32(const void* p) {
    return (uint32_t)__cvta_generic_to_shared(p);
}
__device__ __forceinline__ void cp_async16(uint32_t dst, const void* src) {
    asm volatile("cp.async.cg.shared.global [%0], [%1], 16;\n" :: "r"(dst), "l"(src));
}
__device__ __forceinline__ void cp_commit() {
    asm volatile("cp.async.commit_group;\n" ::: "memory");
}
template<int N> __device__ __forceinline__ void cp_wait() {
    asm volatile("cp.async.wait_group %0;\n" :: "n"(N) : "memory");
}

// ---------------- gate: fused x->fp16, per-block partial stats --------------
// 256 threads = 8 warps = 8 tokens per block; grid = 512.
__global__ __launch_bounds__(256) void gate_kernel(
        const float* __restrict__ x,
        const unsigned char* __restrict__ pm,
        const float* __restrict__ gw,
        float* __restrict__ gate_out) {
    __shared__ float gw_s[NEXP * DIM];   // 32 KB
    __shared__ float s_colsum[NEXP];
    __shared__ int   s_counts[NEXP];
    __shared__ int   s_top1[NEXP];
    __shared__ int   s_nt;

    const int tid = threadIdx.x;
    if (tid < NEXP) { s_colsum[tid] = 0.f; s_counts[tid] = 0; s_top1[tid] = 0; }
    if (tid == 0) s_nt = 0;
    for (int i = tid; i < NEXP * DIM / 4; i += 256)
        ((float4*)gw_s)[i] = ((const float4*)gw)[i];
    __syncthreads();

    const int wid  = tid >> 5;
    const int lane = tid & 31;
    const int n = blockIdx.x * 8 + wid;
    const float* xr = x + (size_t)n * DIM;

    float acc[NEXP];
#pragma unroll
    for (int e = 0; e < NEXP; e++) acc[e] = 0.f;

#pragma unroll
    for (int i = 0; i < DIM / 128; i++) {
        const int d = i * 128 + lane * 4;
        float4 v = *(const float4*)&xr[d];
        __half2 h0 = __floats2half2_rn(v.x, v.y);
        __half2 h1 = __floats2half2_rn(v.z, v.w);
        uint2 o;
        o.x = *(uint32_t*)&h0;
        o.y = *(uint32_t*)&h1;
        *(uint2*)&g_xh[(size_t)n * DIM + d] = o;
#pragma unroll
        for (int e = 0; e < NEXP; e++) {
            const float4 w4 = *(const float4*)&gw_s[e * DIM + d];
            acc[e] += v.x * w4.x + v.y * w4.y + v.z * w4.z + v.w * w4.w;
        }
    }
#pragma unroll
    for (int e = 0; e < NEXP; e++) {
#pragma unroll
        for (int o = 16; o > 0; o >>= 1)
            acc[e] += __shfl_xor_sync(0xffffffffu, acc[e], o);
    }

    if (lane == 0) {
        bool masked = (pm[n] != 0);
        float m = acc[0];
#pragma unroll
        for (int e = 1; e < NEXP; e++) m = fmaxf(m, acc[e]);
        float gv[NEXP]; float s = 0.f;
#pragma unroll
        for (int e = 0; e < NEXP; e++) { gv[e] = expf(acc[e] - m); s += gv[e]; }
        float inv = 1.f / s;
#pragma unroll
        for (int e = 0; e < NEXP; e++) {
            gv[e] *= inv;
            if (masked) gv[e] = 0.f;
            gate_out[(size_t)n * NEXP + e] = gv[e];
        }
        int e1 = 0;
#pragma unroll
        for (int e = 1; e < NEXP; e++) if (gv[e] > gv[e1]) e1 = e;
        int e2 = -1;
#pragma unroll
        for (int e = 0; e < NEXP; e++) {
            if (e == e1) continue;
            if (e2 < 0 || gv[e] > gv[e2]) e2 = e;
        }
        float den = gv[e1] + gv[e2];
        if (den == 0.f) den = 1.f;
        g_tok_e[2 * n + 0] = e1;
        g_tok_e[2 * n + 1] = e2;
        g_tok_w[2 * n + 0] = gv[e1] / den;
        g_tok_w[2 * n + 1] = gv[e2] / den;
        atomicAdd(&s_counts[e1], 1);
        atomicAdd(&s_counts[e2], 1);
        if (!masked) { atomicAdd(&s_top1[e1], 1); atomicAdd(&s_nt, 1); }
#pragma unroll
        for (int e = 0; e < NEXP; e++) atomicAdd(&s_colsum[e], gv[e]);
    }
    __syncthreads();
    if (tid < NEXP) {
        g_part_colsum[blockIdx.x * NEXP + tid] = s_colsum[tid];
        g_part_counts[blockIdx.x * NEXP + tid] = s_counts[tid];
        g_part_top1[blockIdx.x * NEXP + tid]   = s_top1[tid];
    }
    if (tid == 0) g_part_nt[blockIdx.x] = s_nt;
}

// ---------------- route: reduce partials, offsets, loss, zero cursors -------
__global__ void route_kernel(float* __restrict__ loss_out) {
    const int tid = threadIdx.x;
    __shared__ float sh_colsum[NEXP];
    if (tid < NEXP) {
        float cs = 0.f; int cn = 0, t1 = 0;
        for (int b = 0; b < GATE_BLOCKS; b++) {   // deterministic order
            cs += g_part_colsum[b * NEXP + tid];
            cn += g_part_counts[b * NEXP + tid];
            t1 += g_part_top1[b * NEXP + tid];
        }
        g_counts[tid]   = cn;
        g_top1_arr[tid] = t1;
        sh_colsum[tid]  = cs;
        g_cursor[tid]   = 0;
    } else if (tid == 8) {
        int nt = 0;
        for (int b = 0; b < GATE_BLOCKS; b++) nt += g_part_nt[b];
        g_nt = nt;
    }
    __syncthreads();
    if (tid == 0) {
        int off = 0;
        for (int e = 0; e < NEXP; e++) { g_offsets[e] = off; off += g_counts[e]; }
        g_offsets[NEXP] = off;
        float nt = (float)g_nt;
        float s = 0.f;
        for (int e = 0; e < NEXP; e++)
            s += ((float)g_top1_arr[e] / nt) * (sh_colsum[e] / nt);
        *loss_out = (float)NEXP * s;
    }
}

__global__ void scatter_kernel() {
    int n = blockIdx.x * blockDim.x + threadIdx.x;
    if (n >= N_TOK) return;
#pragma unroll
    for (int s = 0; s < 2; s++) {
        int e = g_tok_e[2 * n + s];
        int pos = g_offsets[e] + atomicAdd(&g_cursor[e], 1);
        g_expert_tok[pos] = n;
        g_expert_w[pos]   = g_tok_w[2 * n + s];
    }
}

// ---------------- weight fp32 -> fp16 conversion ----------------------------
template<int WHICH>
__global__ void conv_w_kernel(const float4* __restrict__ src, int n8) {
    uint4* dst = (uint4*)(WHICH == 0 ? g_w1h : g_w2h);
    int stride = gridDim.x * blockDim.x;
    for (int i = blockIdx.x * blockDim.x + threadIdx.x; i < n8; i += stride) {
        float4 v0 = src[2 * i];
        float4 v1 = src[2 * i + 1];
        __half2 h0 = __floats2half2_rn(v0.x, v0.y);
        __half2 h1 = __floats2half2_rn(v0.z, v0.w);
        __half2 h2 = __floats2half2_rn(v1.x, v1.y);
        __half2 h3 = __floats2half2_rn(v1.z, v1.w);
        uint4 o;
        o.x = *(uint32_t*)&h0;
        o.y = *(uint32_t*)&h1;
        o.z = *(uint32_t*)&h2;
        o.w = *(uint32_t*)&h3;
        dst[i] = o;
    }
}

// ---------------- grouped GEMM (per-expert launch) ---------------------------
// MODE 0: g_H = half(relu(Xg @ w1h^T + b1))          KTOT=DIM,  NCOLS=HDIM
// MODE 1: out[tok] += w * (g_H @ w2h^T + b2) atomics  KTOT=HDIM, NCOLS=DIM
template<int KTOT, int MODE>
__global__ __launch_bounds__(NTH, 2) void gemm_kernel(const float* __restrict__ bias,
                                                      float* __restrict__ outp,
                                                      int e) {
    const int off = g_offsets[e];
    const int cnt = g_offsets[e + 1] - off;
    const int row0 = blockIdx.y * TM;
    if (row0 >= cnt) return;
    const int n0 = blockIdx.x * TN;
    const int NCOLS = (MODE == 0) ? HDIM : DIM;

    extern __shared__ __align__(16) __half sh[];

    const int tid  = threadIdx.x;
    const int warp = tid >> 5;
    const int wm   = warp >> 1;
    const int wn   = warp & 1;

    const __half* Bbase = (MODE == 0) ? g_w1h : g_w2h;

    const __half* a_src[4];
    uint32_t a_off[4];
    const __half* b_src[4];
    uint32_t b_off[4];
#pragma unroll
    for (int i = 0; i < 4; i++) {
        int cid = tid + i * NTH;
        int r   = cid >> 2;
        int c8  = (cid & 3) * 8;
        int slot = off + row0 + r;
        if (slot > NSLOT - 1) slot = NSLOT - 1;
        if (MODE == 0) {
            int tok = g_expert_tok[slot];
            a_src[i] = g_xh + (size_t)tok * DIM + c8;
        } else {
            a_src[i] = g_H + (size_t)slot * HDIM + c8;
        }
        a_off[i] = (uint32_t)((r * LDB + c8) * 2);
        b_src[i] = Bbase + (size_t)(e * NCOLS + n0 + r) * KTOT + c8;
        b_off[i] = (uint32_t)((TM * LDB + r * LDB + c8) * 2);
    }
    const uint32_t sbase = smem_u32(sh);
    const uint32_t STAGE_B = STAGE_H * 2;

    wmma::fragment<wmma::accumulator, 16, 16, 16, float> acc[4][4];
#pragma unroll
    for (int i = 0; i < 4; i++)
#pragma unroll
        for (int j = 0; j < 4; j++) wmma::fill_fragment(acc[i][j], 0.f);

    const int T = KTOT / BK;

#pragma unroll
    for (int s = 0; s < 2; s++) {
#pragma unroll
        for (int i = 0; i < 4; i++) {
            cp_async16(sbase + s * STAGE_B + a_off[i], a_src[i] + (size_t)s * BK);
            cp_async16(sbase + s * STAGE_B + b_off[i], b_src[i] + (size_t)s * BK);
        }
        cp_commit();
    }

    int buf = 0;
    for (int t = 0; t < T; t++) {
        if (t < T - 1) cp_wait<1>(); else cp_wait<0>();
        __syncthreads();

        if (t + 2 < T) {
            int pb = (buf + 2 >= 3) ? buf - 1 : buf + 2;
            uint32_t pbb = sbase + pb * STAGE_B;
#pragma unroll
            for (int i = 0; i < 4; i++) {
                cp_async16(pbb + a_off[i], a_src[i] + (size_t)(t + 2) * BK);
                cp_async16(pbb + b_off[i], b_src[i] + (size_t)(t + 2) * BK);
            }
            cp_commit();
        }

        const __half* As = sh + (size_t)buf * STAGE_H;
        const __half* Bs = As + TM * LDB;
#pragma unroll
        for (int kk = 0; kk < BK; kk += 16) {
            wmma::fragment<wmma::matrix_a, 16, 16, 16, half, wmma::row_major> af[4];
            wmma::fragment<wmma::matrix_b, 16, 16, 16, half, wmma::col_major> bf[4];
#pragma unroll
            for (int i = 0; i < 4; i++)
                wmma::load_matrix_sync(af[i], &As[(wm * 64 + i * 16) * LDB + kk], LDB);
#pragma unroll
            for (int j = 0; j < 4; j++)
                wmma::load_matrix_sync(bf[j], &Bs[(wn * 64 + j * 16) * LDB + kk], LDB);
#pragma unroll
            for (int i = 0; i < 4; i++)
#pragma unroll
                for (int j = 0; j < 4; j++)
                    wmma::mma_sync(acc[i][j], af[i], bf[j], acc[i][j]);
        }
        buf = (buf + 1 >= 3) ? 0 : buf + 1;
    }
    __syncthreads();

    float* Cs = (float*)sh;
#pragma unroll
    for (int p = 0; p < 2; p++) {
        if (wn == p) {
#pragma unroll
            for (int i = 0; i < 4; i++)
#pragma unroll
                for (int j = 0; j < 4; j++)
                    wmma::store_matrix_sync(&Cs[(wm * 64 + i * 16) * LDC + j * 16],
                                            acc[i][j], LDC, wmma::mem_row_major);
        }
        __syncthreads();

#pragma unroll
        for (int i = 0; i < 16; i++) {
            int idx4 = tid + i * NTH;
            int r    = idx4 >> 4;
            int c4   = (idx4 & 15) * 4;
            if (row0 + r < cnt) {
                int slot = off + row0 + r;
                int col  = n0 + p * 64 + c4;
                float4 v = *(const float4*)&Cs[r * LDC + c4];
                const float4 bv = *(const float4*)&bias[e * NCOLS + col];
                if (MODE == 0) {
                    __half2 h0 = __floats2half2_rn(fmaxf(v.x + bv.x, 0.f),
                                                   fmaxf(v.y + bv.y, 0.f));
                    __half2 h1 = __floats2half2_rn(fmaxf(v.z + bv.z, 0.f),
                                                   fmaxf(v.w + bv.w, 0.f));
                    uint2 o;
                    o.x = *(uint32_t*)&h0;
                    o.y = *(uint32_t*)&h1;
                    *(uint2*)&g_H[(size_t)slot * HDIM + col] = o;
                } else {
                    int tok = g_expert_tok[slot];
                    float w = g_expert_w[slot];
                    float* o = &outp[(size_t)tok * DIM + col];
                    // exactly 2 commutative fp32 adds per element -> deterministic
                    atomicAdd(o + 0, (v.x + bv.x) * w);
                    atomicAdd(o + 1, (v.y + bv.y) * w);
                    atomicAdd(o + 2, (v.z + bv.z) * w);
                    atomicAdd(o + 3, (v.w + bv.w) * w);
                }
            }
        }
        __syncthreads();
    }
}

__global__ void join_kernel() {}

// ---------------- launch -----------------------------------------------------
extern "C" void kernel_launch(void* const* d_in, const int* in_sizes, int n_in,
                              void* d_out, int out_size) {
    const float*         x      = (const float*)d_in[0];
    const unsigned char* pm     = (const unsigned char*)d_in[1];
    const float*         gate_w = (const float*)d_in[2];
    const float*         fc1_w  = (const float*)d_in[3];
    const float*         fc1_b  = (const float*)d_in[4];
    const float*         fc2_w  = (const float*)d_in[5];
    const float*         fc2_b  = (const float*)d_in[6];
    (void)in_sizes; (void)n_in; (void)out_size;

    float* out      = (float*)d_out;
    float* gate_out = out + (size_t)N_TOK * DIM;
    float* loss_out = gate_out + (size_t)N_TOK * NEXP;

    static cudaStream_t st[4] = {nullptr, nullptr, nullptr, nullptr};  // st[0] = default
    static cudaEvent_t evFork = nullptr, evW0 = nullptr, evW1 = nullptr, evRoute = nullptr;
    static cudaEvent_t evDone[4];
    if (st[1] == nullptr) {
        for (int i = 1; i < 4; i++) cudaStreamCreateWithFlags(&st[i], cudaStreamNonBlocking);
        cudaEventCreateWithFlags(&evFork, cudaEventDisableTiming);
        cudaEventCreateWithFlags(&evW0, cudaEventDisableTiming);
        cudaEventCreateWithFlags(&evW1, cudaEventDisableTiming);
        cudaEventCreateWithFlags(&evRoute, cudaEventDisableTiming);
        for (int i = 1; i < 4; i++) cudaEventCreateWithFlags(&evDone[i], cudaEventDisableTiming);
        cudaFuncSetAttribute(gemm_kernel<DIM, 0>,
                             cudaFuncAttributeMaxDynamicSharedMemorySize, SMEM_BYTES);
        cudaFuncSetAttribute(gemm_kernel<HDIM, 1>,
                             cudaFuncAttributeMaxDynamicSharedMemorySize, SMEM_BYTES);
    }

    const dim3 G1(HDIM / TN, NSLOT / TM / 2);   // (16, 32): covers cnt up to 4096
    const dim3 G2(DIM / TN,  NSLOT / TM / 2);   // (8, 32)

    // fork s1: out-zeroing + weight conversion (independent of routing)
    cudaEventRecord(evFork, 0);
    cudaStreamWaitEvent(st[1], evFork, 0);
    cudaMemsetAsync(out, 0, (size_t)N_TOK * DIM * sizeof(float), st[1]);
    conv_w_kernel<0><<<2048, 256, 0, st[1]>>>((const float4*)fc1_w, NEXP * HDIM * DIM / 8);
    cudaEventRecord(evW0, st[1]);
    conv_w_kernel<1><<<2048, 256, 0, st[1]>>>((const float4*)fc2_w, NEXP * DIM * HDIM / 8);
    cudaEventRecord(evW1, st[1]);

    // routing on stream 0
    gate_kernel<<<GATE_BLOCKS, 256>>>(x, pm, gate_w, gate_out);
    route_kernel<<<1, 32>>>(loss_out);
    scatter_kernel<<<N_TOK / 256, 256>>>();
    cudaEventRecord(evRoute, 0);

    // per-expert GEMM pipelines: expert e -> stream e%4 (stream 0 = default)
    // stream 0 (experts 0,4)
    cudaStreamWaitEvent(0, evW0, 0);
    gemm_kernel<DIM, 0><<<G1, NTH, SMEM_BYTES, 0>>>(fc1_b, nullptr, 0);
    cudaStreamWaitEvent(0, evW1, 0);
    gemm_kernel<HDIM, 1><<<G2, NTH, SMEM_BYTES, 0>>>(fc2_b, out, 0);
    gemm_kernel<DIM, 0><<<G1, NTH, SMEM_BYTES, 0>>>(fc1_b, nullptr, 4);
    gemm_kernel<HDIM, 1><<<G2, NTH, SMEM_BYTES, 0>>>(fc2_b, out, 4);

    // streams 1..3 (experts i, i+4)
    for (int i = 1; i < 4; i++) {
        cudaStreamWaitEvent(st[i], evRoute, 0);
        cudaStreamWaitEvent(st[i], evW0, 0);
        gemm_kernel<DIM, 0><<<G1, NTH, SMEM_BYTES, st[i]>>>(fc1_b, nullptr, i);
        cudaStreamWaitEvent(st[i], evW1, 0);
        gemm_kernel<HDIM, 1><<<G2, NTH, SMEM_BYTES, st[i]>>>(fc2_b, out, i);
        gemm_kernel<DIM, 0><<<G1, NTH, SMEM_BYTES, st[i]>>>(fc1_b, nullptr, i + 4);
        gemm_kernel<HDIM, 1><<<G2, NTH, SMEM_BYTES, st[i]>>>(fc2_b, out, i + 4);
        cudaEventRecord(evDone[i], st[i]);
    }

    // join everything back into stream 0
    for (int i = 1; i < 4; i++) cudaStreamWaitEvent(0, evDone[i], 0);
    join_kernel<<<1, 1>>>();
}

// round 16
// speedup vs baseline: 1.1281x; 1.1281x over previous
#include <cuda_runtime.h>
#include <cuda_fp16.h>
#include <mma.h>
#include <cstdint>

using namespace nvcuda;

#define N_TOK 4096
#define DIM   1024
#define NEXP  8
#define HDIM  2048
#define NSLOT 8192
#define PAD   128
#define GATE_BLOCKS (N_TOK / 8)   // 512

// gemm tiling: block 128x128, 4 warps (2x2), warp tile 64x64, BK=32, 3 stages
#define TM 128
#define TN 128
#define BK 32
#define NTH 128
#define LDB 40            // smem row stride in halves (80B)
#define LDC 68            // epilogue fp32 row stride

#define STAGE_H (TM * LDB + TN * LDB)     // halves per stage (10240)
#define SMEM_BYTES (3 * STAGE_H * 2)      // 61440 B; epilogue overlay 34816 B fits

// ---------------- scratch (device globals) ----------------------------------
__device__ __align__(256) __half g_xh[(size_t)N_TOK * DIM];           // x in fp16
__device__ __align__(256) __half g_H [(size_t)(NSLOT + PAD) * HDIM];  // relu out fp16
__device__ __align__(256) __half g_w1h[(size_t)NEXP * HDIM * DIM];
__device__ __align__(256) __half g_w2h[(size_t)NEXP * DIM * HDIM];
__device__ int   g_expert_tok[NSLOT];
__device__ float g_expert_w[NSLOT];
__device__ int   g_tok_e[N_TOK * 2];
__device__ float g_tok_w[N_TOK * 2];
__device__ int   g_counts[NEXP];
__device__ int   g_cursor[NEXP];
__device__ int   g_offsets[NEXP + 1];
// per-gate-block partials (plain stores in gate; reduced in route_kernel)
__device__ float g_part_colsum[GATE_BLOCKS * NEXP];
__device__ int   g_part_counts[GATE_BLOCKS * NEXP];
__device__ int   g_part_top1[GATE_BLOCKS * NEXP];
__device__ int   g_part_nt[GATE_BLOCKS];

// ---------------- helpers ---------------------------------------------------
__device__ __forceinline__ uint32_t smem_u32(const void* p) {
    return (uint32_t)__cvta_generic_to_shared(p);
}
__device__ __forceinline__ void cp_async16(uint32_t dst, const void* src) {
    asm volatile("cp.async.cg.shared.global [%0], [%1], 16;\n" :: "r"(dst), "l"(src));
}
__device__ __forceinline__ void cp_commit() {
    asm volatile("cp.async.commit_group;\n" ::: "memory");
}
template<int N> __device__ __forceinline__ void cp_wait() {
    asm volatile("cp.async.wait_group %0;\n" :: "n"(N) : "memory");
}

// ---------------- gate: fused x->fp16, per-block partial stats --------------
// 256 threads = 8 warps = 8 tokens per block; grid = 512.
__global__ __launch_bounds__(256) void gate_kernel(
        const float* __restrict__ x,
        const unsigned char* __restrict__ pm,
        const float* __restrict__ gw,
        float* __restrict__ gate_out) {
    __shared__ float gw_s[NEXP * DIM];   // 32 KB
    __shared__ float s_colsum[NEXP];
    __shared__ int   s_counts[NEXP];
    __shared__ int   s_top1[NEXP];
    __shared__ int   s_nt;

    const int tid = threadIdx.x;
    if (tid < NEXP) { s_colsum[tid] = 0.f; s_counts[tid] = 0; s_top1[tid] = 0; }
    if (tid == 0) s_nt = 0;
    for (int i = tid; i < NEXP * DIM / 4; i += 256)
        ((float4*)gw_s)[i] = ((const float4*)gw)[i];
    __syncthreads();

    const int wid  = tid >> 5;
    const int lane = tid & 31;
    const int n = blockIdx.x * 8 + wid;
    const float* xr = x + (size_t)n * DIM;

    float acc[NEXP];
#pragma unroll
    for (int e = 0; e < NEXP; e++) acc[e] = 0.f;

#pragma unroll
    for (int i = 0; i < DIM / 128; i++) {
        const int d = i * 128 + lane * 4;
        float4 v = *(const float4*)&xr[d];
        __half2 h0 = __floats2half2_rn(v.x, v.y);
        __half2 h1 = __floats2half2_rn(v.z, v.w);
        uint2 o;
        o.x = *(uint32_t*)&h0;
        o.y = *(uint32_t*)&h1;
        *(uint2*)&g_xh[(size_t)n * DIM + d] = o;
#pragma unroll
        for (int e = 0; e < NEXP; e++) {
            const float4 w4 = *(const float4*)&gw_s[e * DIM + d];
            acc[e] += v.x * w4.x + v.y * w4.y + v.z * w4.z + v.w * w4.w;
        }
    }
#pragma unroll
    for (int e = 0; e < NEXP; e++) {
#pragma unroll
        for (int o = 16; o > 0; o >>= 1)
            acc[e] += __shfl_xor_sync(0xffffffffu, acc[e], o);
    }

    if (lane == 0) {
        bool masked = (pm[n] != 0);
        float m = acc[0];
#pragma unroll
        for (int e = 1; e < NEXP; e++) m = fmaxf(m, acc[e]);
        float gv[NEXP]; float s = 0.f;
#pragma unroll
        for (int e = 0; e < NEXP; e++) { gv[e] = expf(acc[e] - m); s += gv[e]; }
        float inv = 1.f / s;
#pragma unroll
        for (int e = 0; e < NEXP; e++) {
            gv[e] *= inv;
            if (masked) gv[e] = 0.f;
            gate_out[(size_t)n * NEXP + e] = gv[e];
        }
        int e1 = 0;
#pragma unroll
        for (int e = 1; e < NEXP; e++) if (gv[e] > gv[e1]) e1 = e;
        int e2 = -1;
#pragma unroll
        for (int e = 0; e < NEXP; e++) {
            if (e == e1) continue;
            if (e2 < 0 || gv[e] > gv[e2]) e2 = e;
        }
        float den = gv[e1] + gv[e2];
        if (den == 0.f) den = 1.f;
        g_tok_e[2 * n + 0] = e1;
        g_tok_e[2 * n + 1] = e2;
        g_tok_w[2 * n + 0] = gv[e1] / den;
        g_tok_w[2 * n + 1] = gv[e2] / den;
        atomicAdd(&s_counts[e1], 1);
        atomicAdd(&s_counts[e2], 1);
        if (!masked) { atomicAdd(&s_top1[e1], 1); atomicAdd(&s_nt, 1); }
#pragma unroll
        for (int e = 0; e < NEXP; e++) atomicAdd(&s_colsum[e], gv[e]);
    }
    __syncthreads();
    if (tid < NEXP) {
        g_part_colsum[blockIdx.x * NEXP + tid] = s_colsum[tid];
        g_part_counts[blockIdx.x * NEXP + tid] = s_counts[tid];
        g_part_top1[blockIdx.x * NEXP + tid]   = s_top1[tid];
    }
    if (tid == 0) g_part_nt[blockIdx.x] = s_nt;
}

// ---------------- route: parallel reduce, offsets, loss, zero cursors -------
// 256 threads = 8 warps. Warp w reduces expert w (lane sums 16 strided blocks,
// butterfly combine: fixed order -> deterministic). Warp 0 also reduces nt.
__global__ __launch_bounds__(256) void route_kernel(float* __restrict__ loss_out) {
    const int tid  = threadIdx.x;
    const int wid  = tid >> 5;     // expert
    const int lane = tid & 31;
    __shared__ float sh_colsum[NEXP];
    __shared__ int   sh_counts[NEXP];
    __shared__ int   sh_top1[NEXP];
    __shared__ int   sh_nt;

    float cs = 0.f; int cn = 0, t1 = 0;
#pragma unroll
    for (int k = 0; k < GATE_BLOCKS / 32; k++) {   // 16 blocks per lane
        int b = k * 32 + lane;
        cs += g_part_colsum[b * NEXP + wid];
        cn += g_part_counts[b * NEXP + wid];
        t1 += g_part_top1[b * NEXP + wid];
    }
#pragma unroll
    for (int o = 16; o > 0; o >>= 1) {
        cs += __shfl_xor_sync(0xffffffffu, cs, o);
        cn += __shfl_xor_sync(0xffffffffu, cn, o);
        t1 += __shfl_xor_sync(0xffffffffu, t1, o);
    }
    if (lane == 0) {
        sh_colsum[wid] = cs;
        sh_counts[wid] = cn;
        sh_top1[wid]   = t1;
        g_counts[wid]  = cn;
        g_cursor[wid]  = 0;
    }
    if (wid == 0) {
        int nt = 0;
#pragma unroll
        for (int k = 0; k < GATE_BLOCKS / 32; k++) nt += g_part_nt[k * 32 + lane];
#pragma unroll
        for (int o = 16; o > 0; o >>= 1) nt += __shfl_xor_sync(0xffffffffu, nt, o);
        if (lane == 0) sh_nt = nt;
    }
    __syncthreads();
    if (tid == 0) {
        int off = 0;
        for (int e = 0; e < NEXP; e++) { g_offsets[e] = off; off += sh_counts[e]; }
        g_offsets[NEXP] = off;
        float nt = (float)sh_nt;
        float s = 0.f;
        for (int e = 0; e < NEXP; e++)
            s += ((float)sh_top1[e] / nt) * (sh_colsum[e] / nt);
        *loss_out = (float)NEXP * s;
    }
}

__global__ void scatter_kernel() {
    int n = blockIdx.x * blockDim.x + threadIdx.x;
    if (n >= N_TOK) return;
#pragma unroll
    for (int s = 0; s < 2; s++) {
        int e = g_tok_e[2 * n + s];
        int pos = g_offsets[e] + atomicAdd(&g_cursor[e], 1);
        g_expert_tok[pos] = n;
        g_expert_w[pos]   = g_tok_w[2 * n + s];
    }
}

// ---------------- weight fp32 -> fp16 conversion ----------------------------
template<int WHICH>
__global__ void conv_w_kernel(const float4* __restrict__ src, int n8) {
    uint4* dst = (uint4*)(WHICH == 0 ? g_w1h : g_w2h);
    int stride = gridDim.x * blockDim.x;
    for (int i = blockIdx.x * blockDim.x + threadIdx.x; i < n8; i += stride) {
        float4 v0 = src[2 * i];
        float4 v1 = src[2 * i + 1];
        __half2 h0 = __floats2half2_rn(v0.x, v0.y);
        __half2 h1 = __floats2half2_rn(v0.z, v0.w);
        __half2 h2 = __floats2half2_rn(v1.x, v1.y);
        __half2 h3 = __floats2half2_rn(v1.z, v1.w);
        uint4 o;
        o.x = *(uint32_t*)&h0;
        o.y = *(uint32_t*)&h1;
        o.z = *(uint32_t*)&h2;
        o.w = *(uint32_t*)&h3;
        dst[i] = o;
    }
}

// ---------------- grouped GEMM (per-expert launch) ---------------------------
// MODE 0: g_H = half(relu(Xg @ w1h^T + b1))          KTOT=DIM,  NCOLS=HDIM
// MODE 1: out[tok] += w * (g_H @ w2h^T + b2) atomics  KTOT=HDIM, NCOLS=DIM
template<int KTOT, int MODE>
__global__ __launch_bounds__(NTH, 2) void gemm_kernel(const float* __restrict__ bias,
                                                      float* __restrict__ outp,
                                                      int e) {
    const int off = g_offsets[e];
    const int cnt = g_offsets[e + 1] - off;
    const int row0 = blockIdx.y * TM;
    if (row0 >= cnt) return;
    const int n0 = blockIdx.x * TN;
    const int NCOLS = (MODE == 0) ? HDIM : DIM;

    extern __shared__ __align__(16) __half sh[];

    const int tid  = threadIdx.x;
    const int warp = tid >> 5;
    const int wm   = warp >> 1;
    const int wn   = warp & 1;

    const __half* Bbase = (MODE == 0) ? g_w1h : g_w2h;

    const __half* a_src[4];
    uint32_t a_off[4];
    const __half* b_src[4];
    uint32_t b_off[4];
#pragma unroll
    for (int i = 0; i < 4; i++) {
        int cid = tid + i * NTH;
        int r   = cid >> 2;
        int c8  = (cid & 3) * 8;
        int slot = off + row0 + r;
        if (slot > NSLOT - 1) slot = NSLOT - 1;
        if (MODE == 0) {
            int tok = g_expert_tok[slot];
            a_src[i] = g_xh + (size_t)tok * DIM + c8;
        } else {
            a_src[i] = g_H + (size_t)slot * HDIM + c8;
        }
        a_off[i] = (uint32_t)((r * LDB + c8) * 2);
        b_src[i] = Bbase + (size_t)(e * NCOLS + n0 + r) * KTOT + c8;
        b_off[i] = (uint32_t)((TM * LDB + r * LDB + c8) * 2);
    }
    const uint32_t sbase = smem_u32(sh);
    const uint32_t STAGE_B = STAGE_H * 2;

    wmma::fragment<wmma::accumulator, 16, 16, 16, float> acc[4][4];
#pragma unroll
    for (int i = 0; i < 4; i++)
#pragma unroll
        for (int j = 0; j < 4; j++) wmma::fill_fragment(acc[i][j], 0.f);

    const int T = KTOT / BK;

#pragma unroll
    for (int s = 0; s < 2; s++) {
#pragma unroll
        for (int i = 0; i < 4; i++) {
            cp_async16(sbase + s * STAGE_B + a_off[i], a_src[i] + (size_t)s * BK);
            cp_async16(sbase + s * STAGE_B + b_off[i], b_src[i] + (size_t)s * BK);
        }
        cp_commit();
    }

    int buf = 0;
    for (int t = 0; t < T; t++) {
        if (t < T - 1) cp_wait<1>(); else cp_wait<0>();
        __syncthreads();

        if (t + 2 < T) {
            int pb = (buf + 2 >= 3) ? buf - 1 : buf + 2;
            uint32_t pbb = sbase + pb * STAGE_B;
#pragma unroll
            for (int i = 0; i < 4; i++) {
                cp_async16(pbb + a_off[i], a_src[i] + (size_t)(t + 2) * BK);
                cp_async16(pbb + b_off[i], b_src[i] + (size_t)(t + 2) * BK);
            }
            cp_commit();
        }

        const __half* As = sh + (size_t)buf * STAGE_H;
        const __half* Bs = As + TM * LDB;
#pragma unroll
        for (int kk = 0; kk < BK; kk += 16) {
            wmma::fragment<wmma::matrix_a, 16, 16, 16, half, wmma::row_major> af[4];
            wmma::fragment<wmma::matrix_b, 16, 16, 16, half, wmma::col_major> bf[4];
#pragma unroll
            for (int i = 0; i < 4; i++)
                wmma::load_matrix_sync(af[i], &As[(wm * 64 + i * 16) * LDB + kk], LDB);
#pragma unroll
            for (int j = 0; j < 4; j++)
                wmma::load_matrix_sync(bf[j], &Bs[(wn * 64 + j * 16) * LDB + kk], LDB);
#pragma unroll
            for (int i = 0; i < 4; i++)
#pragma unroll
                for (int j = 0; j < 4; j++)
                    wmma::mma_sync(acc[i][j], af[i], bf[j], acc[i][j]);
        }
        buf = (buf + 1 >= 3) ? 0 : buf + 1;
    }
    __syncthreads();

    float* Cs = (float*)sh;
#pragma unroll
    for (int p = 0; p < 2; p++) {
        if (wn == p) {
#pragma unroll
            for (int i = 0; i < 4; i++)
#pragma unroll
                for (int j = 0; j < 4; j++)
                    wmma::store_matrix_sync(&Cs[(wm * 64 + i * 16) * LDC + j * 16],
                                            acc[i][j], LDC, wmma::mem_row_major);
        }
        __syncthreads();

#pragma unroll
        for (int i = 0; i < 16; i++) {
            int idx4 = tid + i * NTH;
            int r    = idx4 >> 4;
            int c4   = (idx4 & 15) * 4;
            if (row0 + r < cnt) {
                int slot = off + row0 + r;
                int col  = n0 + p * 64 + c4;
                float4 v = *(const float4*)&Cs[r * LDC + c4];
                const float4 bv = *(const float4*)&bias[e * NCOLS + col];
                if (MODE == 0) {
                    __half2 h0 = __floats2half2_rn(fmaxf(v.x + bv.x, 0.f),
                                                   fmaxf(v.y + bv.y, 0.f));
                    __half2 h1 = __floats2half2_rn(fmaxf(v.z + bv.z, 0.f),
                                                   fmaxf(v.w + bv.w, 0.f));
                    uint2 o;
                    o.x = *(uint32_t*)&h0;
                    o.y = *(uint32_t*)&h1;
                    *(uint2*)&g_H[(size_t)slot * HDIM + col] = o;
                } else {
                    int tok = g_expert_tok[slot];
                    float w = g_expert_w[slot];
                    float* o = &outp[(size_t)tok * DIM + col];
                    // exactly 2 commutative fp32 adds per element -> deterministic
                    atomicAdd(o + 0, (v.x + bv.x) * w);
                    atomicAdd(o + 1, (v.y + bv.y) * w);
                    atomicAdd(o + 2, (v.z + bv.z) * w);
                    atomicAdd(o + 3, (v.w + bv.w) * w);
                }
            }
        }
        __syncthreads();
    }
}

__global__ void join_kernel() {}

// ---------------- launch -----------------------------------------------------
extern "C" void kernel_launch(void* const* d_in, const int* in_sizes, int n_in,
                              void* d_out, int out_size) {
    const float*         x      = (const float*)d_in[0];
    const unsigned char* pm     = (const unsigned char*)d_in[1];
    const float*         gate_w = (const float*)d_in[2];
    const float*         fc1_w  = (const float*)d_in[3];
    const float*         fc1_b  = (const float*)d_in[4];
    const float*         fc2_w  = (const float*)d_in[5];
    const float*         fc2_b  = (const float*)d_in[6];
    (void)in_sizes; (void)n_in; (void)out_size;

    float* out      = (float*)d_out;
    float* gate_out = out + (size_t)N_TOK * DIM;
    float* loss_out = gate_out + (size_t)N_TOK * NEXP;

    static cudaStream_t st[4] = {nullptr, nullptr, nullptr, nullptr};  // st[0] = default
    static cudaEvent_t evFork = nullptr, evW0 = nullptr, evW1 = nullptr, evRoute = nullptr;
    static cudaEvent_t evDone[4];
    if (st[1] == nullptr) {
        for (int i = 1; i < 4; i++) cudaStreamCreateWithFlags(&st[i], cudaStreamNonBlocking);
        cudaEventCreateWithFlags(&evFork, cudaEventDisableTiming);
        cudaEventCreateWithFlags(&evW0, cudaEventDisableTiming);
        cudaEventCreateWithFlags(&evW1, cudaEventDisableTiming);
        cudaEventCreateWithFlags(&evRoute, cudaEventDisableTiming);
        for (int i = 1; i < 4; i++) cudaEventCreateWithFlags(&evDone[i], cudaEventDisableTiming);
        cudaFuncSetAttribute(gemm_kernel<DIM, 0>,
                             cudaFuncAttributeMaxDynamicSharedMemorySize, SMEM_BYTES);
        cudaFuncSetAttribute(gemm_kernel<HDIM, 1>,
                             cudaFuncAttributeMaxDynamicSharedMemorySize, SMEM_BYTES);
    }

    const dim3 G1(HDIM / TN, NSLOT / TM / 2);   // (16, 32): covers cnt up to 4096
    const dim3 G2(DIM / TN,  NSLOT / TM / 2);   // (8, 32)

    // fork s1: out-zeroing + weight conversion (independent of routing)
    cudaEventRecord(evFork, 0);
    cudaStreamWaitEvent(st[1], evFork, 0);
    cudaMemsetAsync(out, 0, (size_t)N_TOK * DIM * sizeof(float), st[1]);
    conv_w_kernel<0><<<2048, 256, 0, st[1]>>>((const float4*)fc1_w, NEXP * HDIM * DIM / 8);
    cudaEventRecord(evW0, st[1]);
    conv_w_kernel<1><<<2048, 256, 0, st[1]>>>((const float4*)fc2_w, NEXP * DIM * HDIM / 8);
    cudaEventRecord(evW1, st[1]);

    // routing on stream 0
    gate_kernel<<<GATE_BLOCKS, 256>>>(x, pm, gate_w, gate_out);
    route_kernel<<<1, 256>>>(loss_out);
    scatter_kernel<<<N_TOK / 256, 256>>>();
    cudaEventRecord(evRoute, 0);

    // per-expert GEMM pipelines: expert e -> stream e%4 (stream 0 = default)
    // stream 0 (experts 0,4)
    cudaStreamWaitEvent(0, evW0, 0);
    gemm_kernel<DIM, 0><<<G1, NTH, SMEM_BYTES, 0>>>(fc1_b, nullptr, 0);
    cudaStreamWaitEvent(0, evW1, 0);
    gemm_kernel<HDIM, 1><<<G2, NTH, SMEM_BYTES, 0>>>(fc2_b, out, 0);
    gemm_kernel<DIM, 0><<<G1, NTH, SMEM_BYTES, 0>>>(fc1_b, nullptr, 4);
    gemm_kernel<HDIM, 1><<<G2, NTH, SMEM_BYTES, 0>>>(fc2_b, out, 4);

    // streams 1..3 (experts i, i+4)
    for (int i = 1; i < 4; i++) {
        cudaStreamWaitEvent(st[i], evRoute, 0);
        cudaStreamWaitEvent(st[i], evW0, 0);
        gemm_kernel<DIM, 0><<<G1, NTH, SMEM_BYTES, st[i]>>>(fc1_b, nullptr, i);
        cudaStreamWaitEvent(st[i], evW1, 0);
        gemm_kernel<HDIM, 1><<<G2, NTH, SMEM_BYTES, st[i]>>>(fc2_b, out, i);
        gemm_kernel<DIM, 0><<<G1, NTH, SMEM_BYTES, st[i]>>>(fc1_b, nullptr, i + 4);
        gemm_kernel<HDIM, 1><<<G2, NTH, SMEM_BYTES, st[i]>>>(fc2_b, out, i + 4);
        cudaEventRecord(evDone[i], st[i]);
    }

    // join everything back into stream 0
    for (int i = 1; i < 4; i++) cudaStreamWaitEvent(0, evDone[i], 0);
    join_kernel<<<1, 1>>>();
}